// round 7
// baseline (speedup 1.0000x reference)
#include <cuda_runtime.h>
#include <cuda_bf16.h>
#include <cstdint>

#define D      512
#define NCOLS  100000
#define BROWS  1000
#define NFILT  50
#define MPAD   1024
#define NPAD   100096        /* 782*128 */
#define NTILES 782

// ---------------- scratch ----------------
__device__ __align__(16) unsigned short g_qhi[MPAD * D];
__device__ __align__(16) unsigned short g_qlo[MPAD * D];
__device__ __align__(16) unsigned short g_bhi[(size_t)NPAD * D];   // [n][k] K-major
__device__ __align__(16) unsigned short g_blo[(size_t)NPAD * D];
__device__ float g_T[BROWS];

// ---------------- helpers (sm_80-class PTX only) ----------------
__device__ __forceinline__ uint32_t smem_u32(const void* p) {
    uint32_t a;
    asm("{ .reg .u64 t; cvta.to.shared.u64 t, %1; cvt.u32.u64 %0, t; }" : "=r"(a) : "l"(p));
    return a;
}
__device__ __forceinline__ void cp16(uint32_t dst, const void* src) {
    asm volatile("cp.async.cg.shared.global [%0], [%1], 16;" :: "r"(dst), "l"(src));
}
__device__ __forceinline__ void ldm4(uint32_t* r, uint32_t a) {
    asm volatile("ldmatrix.sync.aligned.m8n8.x4.shared.b16 {%0,%1,%2,%3}, [%4];"
                 : "=r"(r[0]), "=r"(r[1]), "=r"(r[2]), "=r"(r[3]) : "r"(a));
}
__device__ __forceinline__ void mma4(float* c, const uint32_t* a, uint32_t b0, uint32_t b1) {
    asm volatile("mma.sync.aligned.m16n8k16.row.col.f32.bf16.bf16.f32 "
                 "{%0,%1,%2,%3}, {%4,%5,%6,%7}, {%8,%9}, {%0,%1,%2,%3};"
                 : "+f"(c[0]), "+f"(c[1]), "+f"(c[2]), "+f"(c[3])
                 : "r"(a[0]), "r"(a[1]), "r"(a[2]), "r"(a[3]), "r"(b0), "r"(b1));
}
__device__ __forceinline__ void split4(const float* x, unsigned int* hiw, unsigned int* low) {
    #pragma unroll
    for (int p = 0; p < 2; p++) {
        unsigned int u0 = __float_as_uint(x[2 * p]);
        unsigned int u1 = __float_as_uint(x[2 * p + 1]);
        hiw[p] = __byte_perm(u0, u1, 0x7632);
        float h0 = __uint_as_float(u0 & 0xFFFF0000u);
        float h1 = __uint_as_float(u1 & 0xFFFF0000u);
        __nv_bfloat162 lp = __floats2bfloat162_rn(x[2 * p] - h0, x[2 * p + 1] - h1);
        low[p] = *(unsigned int*)&lp;
    }
}

// ---------------------------------------------------------------------------
// convert q -> hi/lo bf16, padded to 1024 rows (pad rows zero)
// ---------------------------------------------------------------------------
__global__ void conv_q_kernel(const float* __restrict__ q) {
    int gid  = blockIdx.x * 256 + threadIdx.x;
    int base = gid * 8;
    if (base >= MPAD * D) return;
    int row = base >> 9;
    float x[8];
    if (row < BROWS) {
        float4 f0 = *(const float4*)(q + base);
        float4 f1 = *(const float4*)(q + base + 4);
        x[0]=f0.x; x[1]=f0.y; x[2]=f0.z; x[3]=f0.w;
        x[4]=f1.x; x[5]=f1.y; x[6]=f1.z; x[7]=f1.w;
    } else {
        #pragma unroll
        for (int i = 0; i < 8; i++) x[i] = 0.f;
    }
    unsigned int hiw[4], low[4];
    split4(x, hiw, low);
    split4(x + 4, hiw + 2, low + 2);
    *(uint4*)(g_qhi + base) = make_uint4(hiw[0], hiw[1], hiw[2], hiw[3]);
    *(uint4*)(g_qlo + base) = make_uint4(low[0], low[1], low[2], low[3]);
}

// ---------------------------------------------------------------------------
// transpose + convert rhs[k][n] fp32 -> g_bhi/g_blo[n][k] bf16 (K-major)
// tile 64k x 128n, 256 threads
// ---------------------------------------------------------------------------
__global__ void __launch_bounds__(256)
conv_rhsT_kernel(const float* __restrict__ rhs) {
    __shared__ float st[128][68];
    int t  = threadIdx.x;
    int nb = blockIdx.x * 128;
    int kb = blockIdx.y * 64;

    int r  = t >> 5;
    int c4 = t & 31;
    int n0 = nb + c4 * 4;
    #pragma unroll
    for (int rr = 0; rr < 8; rr++) {
        int krow = rr * 8 + r;
        float4 v;
        const float* src = rhs + (size_t)(kb + krow) * NCOLS + n0;
        if (n0 + 3 < NCOLS) {
            v = *(const float4*)src;
        } else {
            v.x = (n0 + 0 < NCOLS) ? src[0] : 0.f;
            v.y = (n0 + 1 < NCOLS) ? src[1] : 0.f;
            v.z = (n0 + 2 < NCOLS) ? src[2] : 0.f;
            v.w = (n0 + 3 < NCOLS) ? src[3] : 0.f;
        }
        st[c4 * 4 + 0][krow] = v.x;
        st[c4 * 4 + 1][krow] = v.y;
        st[c4 * 4 + 2][krow] = v.z;
        st[c4 * 4 + 3][krow] = v.w;
    }
    __syncthreads();

    int n    = t >> 1;
    int koff = (t & 1) * 32;
    unsigned int hiw[16], low[16];
    #pragma unroll
    for (int jj = 0; jj < 8; jj++) {
        float x[4];
        *(float4*)x = *(const float4*)&st[n][koff + jj * 4];
        split4(x, hiw + jj * 2, low + jj * 2);
    }
    size_t o = (size_t)(nb + n) * D + kb + koff;
    #pragma unroll
    for (int s = 0; s < 4; s++) {
        *(uint4*)(g_bhi + o + s * 8) = make_uint4(hiw[s*4], hiw[s*4+1], hiw[s*4+2], hiw[s*4+3]);
        *(uint4*)(g_blo + o + s * 8) = make_uint4(low[s*4], low[s*4+1], low[s*4+2], low[s*4+3]);
    }
}

// ---------------------------------------------------------------------------
// prep: target score t[b] from split K-major arrays (contiguous reads) and
// out[b] = 1 - #(unique filtered j with s_j >= t)
// ---------------------------------------------------------------------------
__global__ void __launch_bounds__(128)
prep_kernel(const float* __restrict__ q,
            const int* __restrict__ fidx, const int* __restrict__ tgt,
            float* __restrict__ out) {
    int b = blockIdx.x;
    __shared__ int   list[NFILT + 1];
    __shared__ float sv[NFILT + 1];
    __shared__ float qs[D];
    int tid = threadIdx.x, wid = tid >> 5, lane = tid & 31;
    for (int k = tid; k < D; k += 128) qs[k] = q[b * D + k];
    if (tid < NFILT)  list[tid]   = min(max(fidx[b * NFILT + tid], 0), NCOLS - 1);
    if (tid == NFILT) list[NFILT] = min(max(tgt[b], 0), NCOLS - 1);
    __syncthreads();
    for (int d = wid; d <= NFILT; d += 4) {
        int j = list[d];
        const uint4* bh = (const uint4*)(g_bhi + (size_t)j * D);
        const uint4* bl = (const uint4*)(g_blo + (size_t)j * D);
        float acc = 0.f;
        #pragma unroll
        for (int v = 0; v < 2; v++) {
            uint4 h = bh[lane * 2 + v];
            uint4 l = bl[lane * 2 + v];
            unsigned int hw[4] = { h.x, h.y, h.z, h.w };
            unsigned int lw[4] = { l.x, l.y, l.z, l.w };
            int k0 = lane * 16 + v * 8;
            #pragma unroll
            for (int w = 0; w < 4; w++) {
                __nv_bfloat162 hb = *(__nv_bfloat162*)&hw[w];
                __nv_bfloat162 lb = *(__nv_bfloat162*)&lw[w];
                float b0 = __bfloat162float(hb.x) + __bfloat162float(lb.x);
                float b1 = __bfloat162float(hb.y) + __bfloat162float(lb.y);
                acc = fmaf(qs[k0 + w * 2 + 0], b0, acc);
                acc = fmaf(qs[k0 + w * 2 + 1], b1, acc);
            }
        }
        #pragma unroll
        for (int o = 16; o; o >>= 1) acc += __shfl_xor_sync(0xFFFFFFFFu, acc, o);
        if (lane == 0) sv[d] = acc;
    }
    __syncthreads();
    if (tid == 0) {
        float tv = sv[NFILT];
        g_T[b] = tv;
        float corr = 0.f;
        for (int i = 0; i <= NFILT; i++) {
            bool uniq = true;
            for (int jj = 0; jj < i; jj++)
                if (list[jj] == list[i]) { uniq = false; break; }
            if (uniq && sv[i] >= tv) corr += 1.f;
        }
        out[b] = 1.f - corr;
    }
}

// ---------------------------------------------------------------------------
// main GEMM (mma.sync bf16 split) + fused rank count
// CTA 256m x 128n, 8 warps (4m x 2n), warp 64x64.
// 3-stage cp.async pipeline, K=32 per stage, ONE barrier per chunk,
// loads issued after the barrier so they overlap the whole compute phase.
// A smem: bf16, row stride 80B. B smem: bf16 K-major [n][k0..31], stride 80B.
// ---------------------------------------------------------------------------
#define A_BYTES    20480                    /* 256 rows * 80B, per hi/lo */
#define B_OFF      (2 * A_BYTES)            /* 40960 */
#define B_BYTES    10240                    /* 128 rows * 80B, per hi/lo */
#define STG_BYTES  (B_OFF + 2 * B_BYTES)    /* 61440 */
#define NSTAGE     3
#define SMEM_TOT   (NSTAGE * STG_BYTES)     /* 184320 */
#define NCHUNK     16

__global__ void __launch_bounds__(256, 1)
gemm_mma_kernel(float* __restrict__ out) {
    extern __shared__ char smem[];
    uint32_t sb = smem_u32(smem);
    const int tid = threadIdx.x, lane = tid & 31, wid = tid >> 5;
    const int warpM = wid & 3, warpN = wid >> 2;
    const int mRow0 = blockIdx.x * 256;
    const int nBase = blockIdx.y * 128;

    float c[4][8][4];
    #pragma unroll
    for (int a = 0; a < 4; a++)
        #pragma unroll
        for (int b = 0; b < 8; b++)
            #pragma unroll
            for (int e = 0; e < 4; e++) c[a][b][e] = 0.f;

    auto load_chunk = [&](int ch, int slot) {
        uint32_t base = sb + slot * STG_BYTES;
        int k0 = ch * 32;
        #pragma unroll
        for (int i = 0; i < 4; i++) {                 // A hi/lo: 1024 16B segs each
            int idx = tid + i * 256;
            int r = idx >> 2, seg = idx & 3;
            uint32_t dst = base + r * 80 + seg * 16;
            size_t go = (size_t)(mRow0 + r) * D + k0 + seg * 8;
            cp16(dst,           g_qhi + go);
            cp16(dst + A_BYTES, g_qlo + go);
        }
        #pragma unroll
        for (int i = 0; i < 2; i++) {                 // B hi/lo: 512 16B segs each
            int idx = tid + i * 256;
            int r = idx >> 2, seg = idx & 3;
            uint32_t dst = base + B_OFF + r * 80 + seg * 16;
            size_t go = (size_t)(nBase + r) * D + k0 + seg * 8;
            cp16(dst,           g_bhi + go);
            cp16(dst + B_BYTES, g_blo + go);
        }
        asm volatile("cp.async.commit_group;" ::: "memory");
    };

    // prologue: chunks 0 and 1 in flight
    load_chunk(0, 0);
    load_chunk(1, 1);

    for (int ch = 0; ch < NCHUNK; ch++) {
        if (ch == NCHUNK - 1)
            asm volatile("cp.async.wait_group 0;" ::: "memory");
        else
            asm volatile("cp.async.wait_group 1;" ::: "memory");
        __syncthreads();

        // issue next-next chunk: writes slot (ch+2)%3 == (ch-1)%3, which every
        // warp finished computing before this barrier -> safe, fully overlapped
        if (ch + 2 < NCHUNK) load_chunk(ch + 2, (ch + 2) % NSTAGE);

        uint32_t Ab = sb + (ch % NSTAGE) * STG_BYTES;
        uint32_t Bb = Ab + B_OFF;
        #pragma unroll
        for (int k16 = 0; k16 < 2; k16++) {
            uint32_t AH[4][4], AL[4][4];
            {
                int ar  = warpM * 64 + ((lane >> 3) & 1) * 8 + (lane & 7);
                int aks = k16 * 2 + (lane >> 4);
                #pragma unroll
                for (int mt = 0; mt < 4; mt++) {
                    uint32_t addr = Ab + (ar + mt * 16) * 80 + aks * 16;
                    ldm4(AH[mt], addr);
                    ldm4(AL[mt], addr + A_BYTES);
                }
            }
            uint32_t BH[4][4], BL[4][4];
            {
                int brow  = warpN * 64 + ((lane >> 4) & 1) * 8 + (lane & 7);
                uint32_t boff = k16 * 32 + ((lane >> 3) & 1) * 16;
                #pragma unroll
                for (int nb = 0; nb < 4; nb++) {
                    uint32_t addr = Bb + (brow + nb * 16) * 80 + boff;
                    ldm4(BH[nb], addr);
                    ldm4(BL[nb], addr + B_BYTES);
                }
            }
            #pragma unroll
            for (int p = 0; p < 3; p++) {
                const uint32_t (*Af)[4] = (p == 2) ? AL : AH;
                const uint32_t (*Bf)[4] = (p == 1) ? BL : BH;
                #pragma unroll
                for (int mt = 0; mt < 4; mt++) {
                    #pragma unroll
                    for (int nb = 0; nb < 4; nb++) {
                        mma4(c[mt][2 * nb],     Af[mt], Bf[nb][0], Bf[nb][1]);
                        mma4(c[mt][2 * nb + 1], Af[mt], Bf[nb][2], Bf[nb][3]);
                    }
                }
            }
        }
    }

    // ---- epilogue: count s >= t per row ----
    #pragma unroll
    for (int mt = 0; mt < 4; mt++) {
        #pragma unroll
        for (int h = 0; h < 2; h++) {
            int row = mRow0 + warpM * 64 + mt * 16 + h * 8 + (lane >> 2);
            float tv = (row < BROWS) ? g_T[row] : 0.f;
            float cnt = 0.f;
            #pragma unroll
            for (int nt = 0; nt < 8; nt++) {
                int col = nBase + warpN * 64 + nt * 8 + (lane & 3) * 2;
                if (col < NCOLS) {
                    if (c[mt][nt][h * 2 + 0] >= tv) cnt += 1.f;
                    if (c[mt][nt][h * 2 + 1] >= tv) cnt += 1.f;
                }
            }
            cnt += __shfl_xor_sync(0xFFFFFFFFu, cnt, 1);
            cnt += __shfl_xor_sync(0xFFFFFFFFu, cnt, 2);
            if ((lane & 3) == 0 && row < BROWS && cnt != 0.f)
                atomicAdd(out + row, cnt);
        }
    }
}

// ---------------------------------------------------------------------------
extern "C" void kernel_launch(void* const* d_in, const int* in_sizes, int n_in,
                              void* d_out, int out_size) {
    const float* q    = nullptr;
    const float* rhs  = nullptr;
    const int*   fidx = nullptr;
    const int*   tgt  = nullptr;
    for (int i = 0; i < n_in; i++) {
        switch (in_sizes[i]) {
            case BROWS * D:     q    = (const float*)d_in[i]; break;
            case D * NCOLS:     rhs  = (const float*)d_in[i]; break;
            case BROWS * NFILT: fidx = (const int*)d_in[i];   break;
            case BROWS:         tgt  = (const int*)d_in[i];   break;
        }
    }
    float* out = (float*)d_out;

    cudaFuncSetAttribute(gemm_mma_kernel,
                         cudaFuncAttributeMaxDynamicSharedMemorySize, SMEM_TOT);

    conv_q_kernel<<<256, 256>>>(q);
    conv_rhsT_kernel<<<dim3(NTILES, D / 64), 256>>>(rhs);
    prep_kernel<<<BROWS, 128>>>(q, fidx, tgt, out);
    gemm_mma_kernel<<<dim3(4, NTILES), 256, SMEM_TOT>>>(out);
}

// round 8
// speedup vs baseline: 1.0705x; 1.0705x over previous
#include <cuda_runtime.h>
#include <cuda_bf16.h>
#include <cstdint>

#define D      512
#define NCOLS  100000
#define BROWS  1000
#define NFILT  50
#define MPAD   1024
#define NPAD   100096        /* 782*128 */
#define NTILES 782

// ---------------- scratch ----------------
__device__ __align__(16) unsigned short g_qhi[MPAD * D];
__device__ __align__(16) unsigned short g_qlo[MPAD * D];
__device__ __align__(16) unsigned short g_bhi[(size_t)NPAD * D];   // [n][k] K-major
__device__ __align__(16) unsigned short g_blo[(size_t)NPAD * D];
__device__ float g_T[BROWS];

// ---------------- helpers (sm_80-class PTX only) ----------------
__device__ __forceinline__ uint32_t smem_u32(const void* p) {
    uint32_t a;
    asm("{ .reg .u64 t; cvta.to.shared.u64 t, %1; cvt.u32.u64 %0, t; }" : "=r"(a) : "l"(p));
    return a;
}
__device__ __forceinline__ void cp16(uint32_t dst, const void* src) {
    asm volatile("cp.async.cg.shared.global [%0], [%1], 16;" :: "r"(dst), "l"(src));
}
__device__ __forceinline__ void ldm4(uint32_t* r, uint32_t a) {
    asm volatile("ldmatrix.sync.aligned.m8n8.x4.shared.b16 {%0,%1,%2,%3}, [%4];"
                 : "=r"(r[0]), "=r"(r[1]), "=r"(r[2]), "=r"(r[3]) : "r"(a));
}
__device__ __forceinline__ void mma4(float* c, const uint32_t* a, uint32_t b0, uint32_t b1) {
    asm volatile("mma.sync.aligned.m16n8k16.row.col.f32.bf16.bf16.f32 "
                 "{%0,%1,%2,%3}, {%4,%5,%6,%7}, {%8,%9}, {%0,%1,%2,%3};"
                 : "+f"(c[0]), "+f"(c[1]), "+f"(c[2]), "+f"(c[3])
                 : "r"(a[0]), "r"(a[1]), "r"(a[2]), "r"(a[3]), "r"(b0), "r"(b1));
}
__device__ __forceinline__ void split4(const float* x, unsigned int* hiw, unsigned int* low) {
    #pragma unroll
    for (int p = 0; p < 2; p++) {
        unsigned int u0 = __float_as_uint(x[2 * p]);
        unsigned int u1 = __float_as_uint(x[2 * p + 1]);
        hiw[p] = __byte_perm(u0, u1, 0x7632);
        float h0 = __uint_as_float(u0 & 0xFFFF0000u);
        float h1 = __uint_as_float(u1 & 0xFFFF0000u);
        __nv_bfloat162 lp = __floats2bfloat162_rn(x[2 * p] - h0, x[2 * p + 1] - h1);
        low[p] = *(unsigned int*)&lp;
    }
}

// ---------------------------------------------------------------------------
// convert q -> hi/lo bf16, padded to 1024 rows (pad rows zero)
// ---------------------------------------------------------------------------
__global__ void conv_q_kernel(const float* __restrict__ q) {
    int gid  = blockIdx.x * 256 + threadIdx.x;
    int base = gid * 8;
    if (base >= MPAD * D) return;
    int row = base >> 9;
    float x[8];
    if (row < BROWS) {
        float4 f0 = *(const float4*)(q + base);
        float4 f1 = *(const float4*)(q + base + 4);
        x[0]=f0.x; x[1]=f0.y; x[2]=f0.z; x[3]=f0.w;
        x[4]=f1.x; x[5]=f1.y; x[6]=f1.z; x[7]=f1.w;
    } else {
        #pragma unroll
        for (int i = 0; i < 8; i++) x[i] = 0.f;
    }
    unsigned int hiw[4], low[4];
    split4(x, hiw, low);
    split4(x + 4, hiw + 2, low + 2);
    *(uint4*)(g_qhi + base) = make_uint4(hiw[0], hiw[1], hiw[2], hiw[3]);
    *(uint4*)(g_qlo + base) = make_uint4(low[0], low[1], low[2], low[3]);
}

// ---------------------------------------------------------------------------
// transpose + convert rhs[k][n] fp32 -> g_bhi/g_blo[n][k] bf16 (K-major)
// tile 64k x 128n, 256 threads
// ---------------------------------------------------------------------------
__global__ void __launch_bounds__(256)
conv_rhsT_kernel(const float* __restrict__ rhs) {
    __shared__ float st[128][68];
    int t  = threadIdx.x;
    int nb = blockIdx.x * 128;
    int kb = blockIdx.y * 64;

    int r  = t >> 5;
    int c4 = t & 31;
    int n0 = nb + c4 * 4;
    #pragma unroll
    for (int rr = 0; rr < 8; rr++) {
        int krow = rr * 8 + r;
        float4 v;
        const float* src = rhs + (size_t)(kb + krow) * NCOLS + n0;
        if (n0 + 3 < NCOLS) {
            v = *(const float4*)src;
        } else {
            v.x = (n0 + 0 < NCOLS) ? src[0] : 0.f;
            v.y = (n0 + 1 < NCOLS) ? src[1] : 0.f;
            v.z = (n0 + 2 < NCOLS) ? src[2] : 0.f;
            v.w = (n0 + 3 < NCOLS) ? src[3] : 0.f;
        }
        st[c4 * 4 + 0][krow] = v.x;
        st[c4 * 4 + 1][krow] = v.y;
        st[c4 * 4 + 2][krow] = v.z;
        st[c4 * 4 + 3][krow] = v.w;
    }
    __syncthreads();

    int n    = t >> 1;
    int koff = (t & 1) * 32;
    unsigned int hiw[16], low[16];
    #pragma unroll
    for (int jj = 0; jj < 8; jj++) {
        float x[4];
        *(float4*)x = *(const float4*)&st[n][koff + jj * 4];
        split4(x, hiw + jj * 2, low + jj * 2);
    }
    size_t o = (size_t)(nb + n) * D + kb + koff;
    #pragma unroll
    for (int s = 0; s < 4; s++) {
        *(uint4*)(g_bhi + o + s * 8) = make_uint4(hiw[s*4], hiw[s*4+1], hiw[s*4+2], hiw[s*4+3]);
        *(uint4*)(g_blo + o + s * 8) = make_uint4(low[s*4], low[s*4+1], low[s*4+2], low[s*4+3]);
    }
}

// ---------------------------------------------------------------------------
// prep: target score t[b] from split K-major arrays (contiguous reads) and
// out[b] = 1 - #(unique filtered j with s_j >= t)
// ---------------------------------------------------------------------------
__global__ void __launch_bounds__(128)
prep_kernel(const float* __restrict__ q,
            const int* __restrict__ fidx, const int* __restrict__ tgt,
            float* __restrict__ out) {
    int b = blockIdx.x;
    __shared__ int   list[NFILT + 1];
    __shared__ float sv[NFILT + 1];
    __shared__ float qs[D];
    int tid = threadIdx.x, wid = tid >> 5, lane = tid & 31;
    for (int k = tid; k < D; k += 128) qs[k] = q[b * D + k];
    if (tid < NFILT)  list[tid]   = min(max(fidx[b * NFILT + tid], 0), NCOLS - 1);
    if (tid == NFILT) list[NFILT] = min(max(tgt[b], 0), NCOLS - 1);
    __syncthreads();
    for (int d = wid; d <= NFILT; d += 4) {
        int j = list[d];
        const uint4* bh = (const uint4*)(g_bhi + (size_t)j * D);
        const uint4* bl = (const uint4*)(g_blo + (size_t)j * D);
        float acc = 0.f;
        #pragma unroll
        for (int v = 0; v < 2; v++) {
            uint4 h = bh[lane * 2 + v];
            uint4 l = bl[lane * 2 + v];
            unsigned int hw[4] = { h.x, h.y, h.z, h.w };
            unsigned int lw[4] = { l.x, l.y, l.z, l.w };
            int k0 = lane * 16 + v * 8;
            #pragma unroll
            for (int w = 0; w < 4; w++) {
                __nv_bfloat162 hb = *(__nv_bfloat162*)&hw[w];
                __nv_bfloat162 lb = *(__nv_bfloat162*)&lw[w];
                float b0 = __bfloat162float(hb.x) + __bfloat162float(lb.x);
                float b1 = __bfloat162float(hb.y) + __bfloat162float(lb.y);
                acc = fmaf(qs[k0 + w * 2 + 0], b0, acc);
                acc = fmaf(qs[k0 + w * 2 + 1], b1, acc);
            }
        }
        #pragma unroll
        for (int o = 16; o; o >>= 1) acc += __shfl_xor_sync(0xFFFFFFFFu, acc, o);
        if (lane == 0) sv[d] = acc;
    }
    __syncthreads();
    if (tid == 0) {
        float tv = sv[NFILT];
        g_T[b] = tv;
        float corr = 0.f;
        for (int i = 0; i <= NFILT; i++) {
            bool uniq = true;
            for (int jj = 0; jj < i; jj++)
                if (list[jj] == list[i]) { uniq = false; break; }
            if (uniq && sv[i] >= tv) corr += 1.f;
        }
        out[b] = 1.f - corr;
    }
}

// ---------------------------------------------------------------------------
// main GEMM (mma.sync bf16 split) + fused rank count
// CTA 128m x 128n, 4 warps (2m x 2n), warp 64x64, OCCUPANCY 2:
// two independent CTAs per SM desynchronize barriers/ldmatrix phases so the
// tensor pipe stays fed during per-CTA bubbles.
// 2-stage cp.async pipeline, K=32/chunk, one barrier per chunk; next chunk's
// loads are issued right after the barrier and overlap the whole compute.
// A/B smem: bf16 K-major rows, stride 80B (conflict-free ldmatrix).
// ---------------------------------------------------------------------------
#define A_BYTES    10240                    /* 128 rows * 80B, per hi/lo */
#define B_OFF      (2 * A_BYTES)            /* 20480 */
#define STG_BYTES  (2 * B_OFF)              /* 40960 */
#define NSTAGE     2
#define SMEM_TOT   (NSTAGE * STG_BYTES)     /* 81920 */
#define NCHUNK     16

__global__ void __launch_bounds__(128, 2)
gemm_mma_kernel(float* __restrict__ out) {
    extern __shared__ char smem[];
    uint32_t sb = smem_u32(smem);
    const int tid = threadIdx.x, lane = tid & 31, wid = tid >> 5;
    const int warpM = wid & 1, warpN = wid >> 1;
    const int mRow0 = blockIdx.x * 128;
    const int nBase = blockIdx.y * 128;

    float c[4][8][4];
    #pragma unroll
    for (int a = 0; a < 4; a++)
        #pragma unroll
        for (int b = 0; b < 8; b++)
            #pragma unroll
            for (int e = 0; e < 4; e++) c[a][b][e] = 0.f;

    auto load_chunk = [&](int ch, int slot) {
        uint32_t base = sb + slot * STG_BYTES;
        int k0 = ch * 32;
        #pragma unroll
        for (int i = 0; i < 4; i++) {                 // A hi/lo: 512 16B segs each
            int idx = tid + i * 128;
            int r = idx >> 2, seg = idx & 3;
            uint32_t dst = base + r * 80 + seg * 16;
            size_t go = (size_t)(mRow0 + r) * D + k0 + seg * 8;
            cp16(dst,           g_qhi + go);
            cp16(dst + A_BYTES, g_qlo + go);
        }
        #pragma unroll
        for (int i = 0; i < 4; i++) {                 // B hi/lo: 512 16B segs each
            int idx = tid + i * 128;
            int r = idx >> 2, seg = idx & 3;
            uint32_t dst = base + B_OFF + r * 80 + seg * 16;
            size_t go = (size_t)(nBase + r) * D + k0 + seg * 8;
            cp16(dst,           g_bhi + go);
            cp16(dst + A_BYTES, g_blo + go);
        }
        asm volatile("cp.async.commit_group;" ::: "memory");
    };

    load_chunk(0, 0);

    for (int ch = 0; ch < NCHUNK; ch++) {
        asm volatile("cp.async.wait_group 0;" ::: "memory");
        __syncthreads();
        // every warp finished computing chunk ch-1 (slot (ch+1)&1) before this
        // barrier -> safe to overwrite; load overlaps the entire compute below
        if (ch + 1 < NCHUNK) load_chunk(ch + 1, (ch + 1) & 1);

        uint32_t Ab = sb + (ch & 1) * STG_BYTES;
        uint32_t Bb = Ab + B_OFF;
        #pragma unroll
        for (int k16 = 0; k16 < 2; k16++) {
            uint32_t AH[4][4], AL[4][4];
            {
                int ar  = warpM * 64 + ((lane >> 3) & 1) * 8 + (lane & 7);
                int aks = k16 * 2 + (lane >> 4);
                #pragma unroll
                for (int mt = 0; mt < 4; mt++) {
                    uint32_t addr = Ab + (ar + mt * 16) * 80 + aks * 16;
                    ldm4(AH[mt], addr);
                    ldm4(AL[mt], addr + A_BYTES);
                }
            }
            uint32_t BH[4][4], BL[4][4];
            {
                int brow  = warpN * 64 + ((lane >> 4) & 1) * 8 + (lane & 7);
                uint32_t boff = k16 * 32 + ((lane >> 3) & 1) * 16;
                #pragma unroll
                for (int nb = 0; nb < 4; nb++) {
                    uint32_t addr = Bb + (brow + nb * 16) * 80 + boff;
                    ldm4(BH[nb], addr);
                    ldm4(BL[nb], addr + A_BYTES);
                }
            }
            #pragma unroll
            for (int p = 0; p < 3; p++) {
                const uint32_t (*Af)[4] = (p == 2) ? AL : AH;
                const uint32_t (*Bf)[4] = (p == 1) ? BL : BH;
                #pragma unroll
                for (int mt = 0; mt < 4; mt++) {
                    #pragma unroll
                    for (int nb = 0; nb < 4; nb++) {
                        mma4(c[mt][2 * nb],     Af[mt], Bf[nb][0], Bf[nb][1]);
                        mma4(c[mt][2 * nb + 1], Af[mt], Bf[nb][2], Bf[nb][3]);
                    }
                }
            }
        }
    }

    // ---- epilogue: count s >= t per row ----
    #pragma unroll
    for (int mt = 0; mt < 4; mt++) {
        #pragma unroll
        for (int h = 0; h < 2; h++) {
            int row = mRow0 + warpM * 64 + mt * 16 + h * 8 + (lane >> 2);
            float tv = (row < BROWS) ? g_T[row] : 0.f;
            float cnt = 0.f;
            #pragma unroll
            for (int nt = 0; nt < 8; nt++) {
                int col = nBase + warpN * 64 + nt * 8 + (lane & 3) * 2;
                if (col < NCOLS) {
                    if (c[mt][nt][h * 2 + 0] >= tv) cnt += 1.f;
                    if (c[mt][nt][h * 2 + 1] >= tv) cnt += 1.f;
                }
            }
            cnt += __shfl_xor_sync(0xFFFFFFFFu, cnt, 1);
            cnt += __shfl_xor_sync(0xFFFFFFFFu, cnt, 2);
            if ((lane & 3) == 0 && row < BROWS && cnt != 0.f)
                atomicAdd(out + row, cnt);
        }
    }
}

// ---------------------------------------------------------------------------
extern "C" void kernel_launch(void* const* d_in, const int* in_sizes, int n_in,
                              void* d_out, int out_size) {
    const float* q    = nullptr;
    const float* rhs  = nullptr;
    const int*   fidx = nullptr;
    const int*   tgt  = nullptr;
    for (int i = 0; i < n_in; i++) {
        switch (in_sizes[i]) {
            case BROWS * D:     q    = (const float*)d_in[i]; break;
            case D * NCOLS:     rhs  = (const float*)d_in[i]; break;
            case BROWS * NFILT: fidx = (const int*)d_in[i];   break;
            case BROWS:         tgt  = (const int*)d_in[i];   break;
        }
    }
    float* out = (float*)d_out;

    cudaFuncSetAttribute(gemm_mma_kernel,
                         cudaFuncAttributeMaxDynamicSharedMemorySize, SMEM_TOT);

    conv_q_kernel<<<256, 256>>>(q);
    conv_rhsT_kernel<<<dim3(NTILES, D / 64), 256>>>(rhs);
    prep_kernel<<<BROWS, 128>>>(q, fidx, tgt, out);
    gemm_mma_kernel<<<dim3(8, NTILES), 128, SMEM_TOT>>>(out);
}